// round 9
// baseline (speedup 1.0000x reference)
#include <cuda_runtime.h>
#include <cuda_fp16.h>
#include <cstdint>

// out = (idx[...,0] >= 0) ? shaded[idx0] : (1,1,1)
// (binary-weight alpha composite keeps only the first fragment; bg_mask on
//  slot 0 overrides the rest — only idx[...,0] matters)

#define MAX_P 131072
#define THREADS 256
#define PX_PER_THREAD 4
#define TILE_PX (THREADS * PX_PER_THREAD)      // 1024 px per CTA
#define KFIX 10                                 // fragments per pixel
#define IDX_TILE_BYTES (TILE_PX * KFIX * 4)     // 40960 B
#define OUT_TILE_FLOATS (TILE_PX * 3)           // 3072 floats = 12288 B

// fp16 rgb packed into 8B: .x = half2(r,g), .y = half2(b,_)
__device__ uint2 g_tab[MAX_P];

__global__ void shade_kernel(const float* __restrict__ features,
                             const float* __restrict__ normals,
                             const float* __restrict__ light_dir,
                             int P) {
    int i = blockIdx.x * blockDim.x + threadIdx.x;
    if (i >= P) return;

    float lx = light_dir[0], ly = light_dir[1], lz = light_dir[2];
    float inv = rsqrtf(lx * lx + ly * ly + lz * lz);
    lx *= inv; ly *= inv; lz *= inv;

    float nx = normals[3 * i + 0];
    float ny = normals[3 * i + 1];
    float nz = normals[3 * i + 2];
    float ndl = fabsf(nx * lx + ny * ly + nz * lz);
    float s = 0.6f + 0.8f * ndl;  // AMBIENT + DIFFUSE * |n.l|

    float r = fminf(fmaxf(features[3 * i + 0] * s, 0.0f), 1.0f);
    float g = fminf(fmaxf(features[3 * i + 1] * s, 0.0f), 1.0f);
    float b = fminf(fmaxf(features[3 * i + 2] * s, 0.0f), 1.0f);

    __half2 rg = __floats2half2_rn(r, g);
    __half2 b0 = __floats2half2_rn(b, 0.0f);
    uint2 packed;
    packed.x = *(unsigned int*)&rg;
    packed.y = *(unsigned int*)&b0;
    g_tab[i] = packed;
}

// One CTA = one contiguous 1024-px tile.
//   in:  ONE cp.async.bulk 40KB gmem->smem of the raw idx slab (TMA pipe,
//        zero L1tex tagged wavefronts). Only tid==0 waits on the mbarrier;
//        everyone else sleeps at __syncthreads (no MIO spin pollution).
//   mid: idx0 via LDS (stride-10 words: 2-way conflicts), random 8B table
//        gathers on L1 (irreducible ~2.07 cyc/px tagged).
//   out: STS to pixel-ordered smem tile, ONE cp.async.bulk 12KB smem->gmem.
__global__ __launch_bounds__(THREADS) void composite_kernel(
        const int* __restrict__ idx,
        float* __restrict__ out,
        int n_pix, int K) {
    __shared__ __align__(16) int   s_idx[TILE_PX * KFIX];
    __shared__ __align__(16) float s_out[OUT_TILE_FLOATS];
    __shared__ __align__(8)  unsigned long long s_mbar;

    const uint2* __restrict__ tab = g_tab;
    int tid  = threadIdx.x;
    int lane = tid & 31;
    int warp = tid >> 5;

    long tile_base = (long)blockIdx.x * TILE_PX;
    bool full = (K == KFIX) && (tile_base + TILE_PX) <= (long)n_pix;
    int  lbase = warp * (32 * PX_PER_THREAD) + lane;   // local px of j=0
    long base  = tile_base + lbase;

    // white in packed-fp16 form: half2(1,1), half2(1,0)
    const unsigned int ONE2 = 0x3C003C00u;
    const unsigned int ONE0 = 0x00003C00u;

    if (full) {
        uint32_t mbar_addr, sidx_addr, sout_addr;
        asm("{ .reg .u64 t; cvta.to.shared.u64 t, %1; cvt.u32.u64 %0, t; }"
            : "=r"(mbar_addr) : "l"(&s_mbar));
        asm("{ .reg .u64 t; cvta.to.shared.u64 t, %1; cvt.u32.u64 %0, t; }"
            : "=r"(sidx_addr) : "l"(s_idx));
        asm("{ .reg .u64 t; cvta.to.shared.u64 t, %1; cvt.u32.u64 %0, t; }"
            : "=r"(sout_addr) : "l"(s_out));

        if (tid == 0) {
            asm volatile("mbarrier.init.shared.b64 [%0], %1;"
                         :: "r"(mbar_addr), "r"(1) : "memory");
            asm volatile("fence.proxy.async.shared::cta;" ::: "memory");
            asm volatile("mbarrier.arrive.expect_tx.shared.b64 _, [%0], %1;"
                         :: "r"(mbar_addr), "r"((unsigned)IDX_TILE_BYTES)
                         : "memory");
            const int* gsrc = idx + tile_base * (long)KFIX;
            asm volatile(
                "cp.async.bulk.shared::cta.global.mbarrier::complete_tx::bytes"
                " [%0], [%1], %2, [%3];"
                :: "r"(sidx_addr), "l"(gsrc), "r"((unsigned)IDX_TILE_BYTES),
                   "r"(mbar_addr)
                : "memory");
            // ONLY this thread waits on the mbarrier (HW-sleep, no warp spin)
            uint32_t done;
            asm volatile(
                "{\n\t.reg .pred p;\n\t"
                "mbarrier.try_wait.parity.acquire.cta.shared::cta.b64 p, [%1], 0;\n\t"
                "selp.b32 %0, 1, 0, p;\n\t}"
                : "=r"(done) : "r"(mbar_addr) : "memory");
            if (!done) {
                asm volatile(
                    "{\n\t.reg .pred P1;\n\t"
                    "WL_%=:\n\t"
                    "mbarrier.try_wait.parity.acquire.cta.shared::cta.b64 P1, [%0], 0, 0x989680;\n\t"
                    "@P1 bra.uni WD_%=;\n\t"
                    "bra.uni WL_%=;\n\t"
                    "WD_%=:\n\t}"
                    :: "r"(mbar_addr) : "memory");
            }
        }
        // everyone else sleeps here; released once tid 0 has the data
        __syncthreads();

        int ids[PX_PER_THREAD];
#pragma unroll
        for (int j = 0; j < PX_PER_THREAD; j++)
            ids[j] = s_idx[(lbase + 32 * j) * KFIX];

        uint2 v[PX_PER_THREAD];
#pragma unroll
        for (int j = 0; j < PX_PER_THREAD; j++)
            v[j] = (ids[j] >= 0) ? __ldg(&tab[ids[j]])
                                 : make_uint2(ONE2, ONE0);

#pragma unroll
        for (int j = 0; j < PX_PER_THREAD; j++) {
            int l = lbase + 32 * j;
            float2 rg = __half22float2(*(__half2*)&v[j].x);
            float2 b0 = __half22float2(*(__half2*)&v[j].y);
            s_out[l * 3 + 0] = rg.x;
            s_out[l * 3 + 1] = rg.y;
            s_out[l * 3 + 2] = b0.x;
        }
        __syncthreads();

        if (tid == 0) {
            float* gdst = out + tile_base * 3;
            asm volatile("fence.proxy.async.shared::cta;" ::: "memory");
            asm volatile(
                "cp.async.bulk.global.shared::cta.bulk_group [%0], [%1], %2;"
                :: "l"(gdst), "r"(sout_addr), "n"(OUT_TILE_FLOATS * 4)
                : "memory");
            asm volatile("cp.async.bulk.commit_group;" ::: "memory");
            asm volatile("cp.async.bulk.wait_group 0;" ::: "memory");
        }
    } else {
        // generic fallback (tail tile or unexpected K): plain LDG/STG path
#pragma unroll
        for (int j = 0; j < PX_PER_THREAD; j++) {
            long p = base + 32 * j;
            if (p < n_pix) {
                int id = __ldcs(&idx[p * (long)K]);
                uint2 vv = (id >= 0) ? __ldg(&tab[id]) : make_uint2(ONE2, ONE0);
                float2 rg = __half22float2(*(__half2*)&vv.x);
                float2 b0 = __half22float2(*(__half2*)&vv.y);
                out[p * 3 + 0] = rg.x;
                out[p * 3 + 1] = rg.y;
                out[p * 3 + 2] = b0.x;
            }
        }
    }
}

extern "C" void kernel_launch(void* const* d_in, const int* in_sizes, int n_in,
                              void* d_out, int out_size) {
    const int*   idx       = (const int*)d_in[0];
    const float* features  = (const float*)d_in[1];
    const float* normals   = (const float*)d_in[2];
    const float* light_dir = (const float*)d_in[3];

    int n_pix = out_size / 3;                 // N*H*W
    int K     = in_sizes[0] / n_pix;          // fragments per pixel (10)
    int P     = in_sizes[1] / 3;              // number of points (100000)
    if (P > MAX_P) P = MAX_P;

    {
        int threads = 256;
        int blocks = (P + threads - 1) / threads;
        shade_kernel<<<blocks, threads>>>(features, normals, light_dir, P);
    }
    {
        int blocks = (int)(((long)n_pix + TILE_PX - 1) / TILE_PX);
        composite_kernel<<<blocks, THREADS>>>(idx, (float*)d_out, n_pix, K);
    }
}

// round 10
// speedup vs baseline: 1.4987x; 1.4987x over previous
#include <cuda_runtime.h>
#include <cuda_fp16.h>
#include <cstdint>

// out = (idx[...,0] >= 0) ? shaded[idx0] : (1,1,1)
// (binary-weight alpha composite keeps only the first fragment; bg_mask on
//  slot 0 overrides the rest — only idx[...,0] matters)

#define MAX_P 131072
#define THREADS 128
#define PX_PER_THREAD 4
#define TILE_PX (THREADS * PX_PER_THREAD)     // 512 px per CTA
#define TILE_OUT_FLOATS (TILE_PX * 3)         // 1536 floats = 6 KB

// fp16 rgb packed into 8B: .x = half2(r,g), .y = half2(b,_)
__device__ uint2 g_tab[MAX_P];

__global__ void shade_kernel(const float* __restrict__ features,
                             const float* __restrict__ normals,
                             const float* __restrict__ light_dir,
                             int P) {
    int i = blockIdx.x * blockDim.x + threadIdx.x;
    if (i >= P) return;

    float lx = light_dir[0], ly = light_dir[1], lz = light_dir[2];
    float inv = rsqrtf(lx * lx + ly * ly + lz * lz);
    lx *= inv; ly *= inv; lz *= inv;

    float nx = normals[3 * i + 0];
    float ny = normals[3 * i + 1];
    float nz = normals[3 * i + 2];
    float ndl = fabsf(nx * lx + ny * ly + nz * lz);
    float s = 0.6f + 0.8f * ndl;  // AMBIENT + DIFFUSE * |n.l|

    float r = fminf(fmaxf(features[3 * i + 0] * s, 0.0f), 1.0f);
    float g = fminf(fmaxf(features[3 * i + 1] * s, 0.0f), 1.0f);
    float b = fminf(fmaxf(features[3 * i + 2] * s, 0.0f), 1.0f);

    __half2 rg = __floats2half2_rn(r, g);
    __half2 b0 = __floats2half2_rn(b, 0.0f);
    uint2 packed;
    packed.x = *(unsigned int*)&rg;
    packed.y = *(unsigned int*)&b0;
    g_tab[i] = packed;
}

// R7 dataflow, finer granularity: one CTA = one contiguous 512-px tile,
// 128 threads, 4096 CTAs (16 resident/SM -> small scheduling tail).
// Phase 1: warp-interleaved strided idx LDGs (10 L1 lines / 32 px).
// Phase 2: random 8B fp16-table gathers (irreducible ~2.07 cyc/px tagged).
// Phase 3: STS to pixel-ordered smem tile, ONE cp.async.bulk 6KB smem->gmem
//          (stores stay off the L1tex tagged-wavefront path).
__global__ __launch_bounds__(THREADS) void composite_kernel(
        const int* __restrict__ idx,
        float* __restrict__ out,
        int n_pix, int K) {
    __shared__ __align__(16) float s_out[TILE_OUT_FLOATS];

    const uint2* __restrict__ tab = g_tab;
    int tid  = threadIdx.x;
    int lane = tid & 31;
    int warp = tid >> 5;

    long tile_base = (long)blockIdx.x * TILE_PX;
    bool full = (tile_base + TILE_PX) <= (long)n_pix;
    int  lbase = warp * (32 * PX_PER_THREAD) + lane;   // local px of j=0
    long base  = tile_base + lbase;

    int ids[PX_PER_THREAD];
#pragma unroll
    for (int j = 0; j < PX_PER_THREAD; j++) {
        long p = base + 32 * j;
        ids[j] = (full || p < n_pix) ? __ldcs(&idx[p * (long)K]) : -1;
    }

    // white in packed-fp16 form: half2(1,1), half2(1,0)
    const unsigned int ONE2 = 0x3C003C00u;
    const unsigned int ONE0 = 0x00003C00u;

    uint2 v[PX_PER_THREAD];
#pragma unroll
    for (int j = 0; j < PX_PER_THREAD; j++) {
        v[j] = (ids[j] >= 0) ? __ldg(&tab[ids[j]]) : make_uint2(ONE2, ONE0);
    }

    if (full) {
#pragma unroll
        for (int j = 0; j < PX_PER_THREAD; j++) {
            int l = lbase + 32 * j;
            float2 rg = __half22float2(*(__half2*)&v[j].x);
            float2 b0 = __half22float2(*(__half2*)&v[j].y);
            s_out[l * 3 + 0] = rg.x;   // stride-3 words across lanes: conflict-free
            s_out[l * 3 + 1] = rg.y;
            s_out[l * 3 + 2] = b0.x;
        }
        __syncthreads();

        if (tid == 0) {
            float* gdst = out + tile_base * 3;
            uint32_t saddr;
            asm("{ .reg .u64 t; cvta.to.shared.u64 t, %1; cvt.u32.u64 %0, t; }"
                : "=r"(saddr) : "l"(s_out));
            asm volatile("fence.proxy.async.shared::cta;" ::: "memory");
            asm volatile(
                "cp.async.bulk.global.shared::cta.bulk_group [%0], [%1], %2;"
                :: "l"(gdst), "r"(saddr), "n"(TILE_OUT_FLOATS * 4)
                : "memory");
            asm volatile("cp.async.bulk.commit_group;" ::: "memory");
            asm volatile("cp.async.bulk.wait_group 0;" ::: "memory");
        }
    } else {
        // partial tail tile: plain scalar stores
#pragma unroll
        for (int j = 0; j < PX_PER_THREAD; j++) {
            long p = base + 32 * j;
            if (p < n_pix) {
                float2 rg = __half22float2(*(__half2*)&v[j].x);
                float2 b0 = __half22float2(*(__half2*)&v[j].y);
                out[p * 3 + 0] = rg.x;
                out[p * 3 + 1] = rg.y;
                out[p * 3 + 2] = b0.x;
            }
        }
    }
}

extern "C" void kernel_launch(void* const* d_in, const int* in_sizes, int n_in,
                              void* d_out, int out_size) {
    const int*   idx       = (const int*)d_in[0];
    const float* features  = (const float*)d_in[1];
    const float* normals   = (const float*)d_in[2];
    const float* light_dir = (const float*)d_in[3];

    int n_pix = out_size / 3;                 // N*H*W
    int K     = in_sizes[0] / n_pix;          // fragments per pixel (10)
    int P     = in_sizes[1] / 3;              // number of points (100000)
    if (P > MAX_P) P = MAX_P;

    {
        int threads = 256;
        int blocks = (P + threads - 1) / threads;
        shade_kernel<<<blocks, threads>>>(features, normals, light_dir, P);
    }
    {
        int blocks = (int)(((long)n_pix + TILE_PX - 1) / TILE_PX);
        composite_kernel<<<blocks, THREADS>>>(idx, (float*)d_out, n_pix, K);
    }
}